// round 2
// baseline (speedup 1.0000x reference)
#include <cuda_runtime.h>

#define Wd 192
#define Hd 192
#define HW (192*192)
#define BATCH 4
#define PIX (BATCH*HW)
#define INC 256
#define NHID 16
#define NLAY 9

// ---------------- scratch (no allocations allowed) ----------------
__device__ float g_h0[BATCH*16*HW];          // 9.4 MB  [b][c][y][x]
__device__ float g_h1[BATCH*16*HW];          // 9.4 MB
__device__ float g_cat[(size_t)BATCH*288*HW];// 170 MB  [b][ch][y][x]
__device__ float g_wt[288*128];              // transposed out_w [i][o]

__constant__ int c_dy8[9] = {-1,-1,-1, 0, 1, 1, 1, 0, 0};
__constant__ int c_dx8[9] = {-1, 0, 1, 1, 1, 0,-1,-1, 0};

// ---------------- packed f32x2 helpers ----------------
union F2U { float2 f; unsigned long long u; };

__device__ __forceinline__ unsigned long long fma2(unsigned long long a,
                                                   unsigned long long b,
                                                   unsigned long long c) {
    unsigned long long d;
    asm("fma.rn.f32x2 %0, %1, %2, %3;" : "=l"(d) : "l"(a), "l"(b), "l"(c));
    return d;
}
__device__ __forceinline__ unsigned long long pack2(float x, float y) {
    F2U t; t.f = make_float2(x, y); return t.u;
}

// ================= K0: transpose out_w (128,288) -> (288,128) =================
__global__ void wt_kernel(const float* __restrict__ out_w) {
    int idx = blockIdx.x * 256 + threadIdx.x;
    if (idx < 128 * 288) {
        int o = idx / 288, i = idx % 288;
        g_wt[i * 128 + o] = out_w[idx];
    }
}

// ================= K1: fused 1x1 + 3x3 projection (256 -> 16, 16) =================
// block (16,8) = 128 threads, tile 16x16 pixels, each thread 2 pixels (rows ty, ty+8)
__global__ void __launch_bounds__(128) proj_kernel(
    const float* __restrict__ cen,
    const float* __restrict__ w0, const float* __restrict__ b0,
    const float* __restrict__ w1, const float* __restrict__ b1)
{
    __shared__ __align__(16) float s_cen[16][18][18]; // chunk of 16 channels, halo 1
    __shared__ __align__(16) float s_w1[16][9][16];   // [ci][tap][o]  (o contiguous -> f32x2 pairs)
    __shared__ __align__(16) float s_w0[16][16];      // [ci][o]

    const int tx = threadIdx.x;            // 0..15
    const int ty = threadIdx.y;            // 0..7
    const int tid = ty * 16 + tx;
    const int x0 = blockIdx.x * 16, y0 = blockIdx.y * 16;
    const int b  = blockIdx.z;

    unsigned long long acc0[2][8], acc1[2][8];
#pragma unroll
    for (int p = 0; p < 2; p++)
#pragma unroll
        for (int o = 0; o < 8; o++) { acc0[p][o] = 0ull; acc1[p][o] = 0ull; }

#pragma unroll 1
    for (int cc = 0; cc < 16; cc++) {
        // stage cen tile chunk (16 ch x 18 x 18), zero padded
        for (int idx = tid; idx < 16 * 324; idx += 128) {
            int ci = idx / 324, rem = idx % 324;
            int ly = rem / 18, lx = rem % 18;
            int gy = y0 - 1 + ly, gx = x0 - 1 + lx;
            float v = 0.f;
            if ((unsigned)gy < (unsigned)Hd && (unsigned)gx < (unsigned)Wd)
                v = cen[(size_t)(b * INC + cc * 16 + ci) * HW + gy * Wd + gx];
            s_cen[ci][ly][lx] = v;
        }
        // stage weights: s_w1[ci][t][o] = w1[o][cc*16+ci][t]
        for (int idx = tid; idx < 2304; idx += 128) {
            int ci = idx / 144, rem = idx % 144;
            int t = rem / 16, o = rem % 16;
            s_w1[ci][t][o] = w1[(o * INC + cc * 16 + ci) * 9 + t];
        }
        for (int ii = tid; ii < 256; ii += 128) {
            int ci = ii / 16, o = ii % 16;
            s_w0[ci][o] = w0[o * INC + cc * 16 + ci];
        }
        __syncthreads();

#pragma unroll 1
        for (int ci = 0; ci < 16; ci++) {
#pragma unroll
            for (int px = 0; px < 2; px++) {
                const int ly = ty + px * 8;
                float v[9];
#pragma unroll
                for (int r = 0; r < 3; r++)
#pragma unroll
                    for (int c = 0; c < 3; c++)
                        v[r * 3 + c] = s_cen[ci][ly + r][tx + c];

                unsigned long long cv = pack2(v[4], v[4]);
                const unsigned long long* w0p =
                    reinterpret_cast<const unsigned long long*>(&s_w0[ci][0]);
#pragma unroll
                for (int o2 = 0; o2 < 8; o2++)
                    acc0[px][o2] = fma2(cv, w0p[o2], acc0[px][o2]);
#pragma unroll
                for (int t = 0; t < 9; t++) {
                    unsigned long long tv = pack2(v[t], v[t]);
                    const unsigned long long* wp =
                        reinterpret_cast<const unsigned long long*>(&s_w1[ci][t][0]);
#pragma unroll
                    for (int o2 = 0; o2 < 8; o2++)
                        acc1[px][o2] = fma2(tv, wp[o2], acc1[px][o2]);
                }
            }
        }
        __syncthreads();
    }

#pragma unroll
    for (int px = 0; px < 2; px++) {
        const int y = y0 + ty + px * 8, x = x0 + tx;
        const size_t base = (size_t)b * 16 * HW + (size_t)y * Wd + x;
#pragma unroll
        for (int o2 = 0; o2 < 8; o2++) {
            F2U a; a.u = acc0[px][o2];
            g_h0[base + (size_t)(2 * o2) * HW]     = a.f.x + b0[2 * o2];
            g_h0[base + (size_t)(2 * o2 + 1) * HW] = a.f.y + b0[2 * o2 + 1];
            F2U c; c.u = acc1[px][o2];
            g_h1[base + (size_t)(2 * o2) * HW]     = c.f.x + b1[2 * o2];
            g_h1[base + (size_t)(2 * o2 + 1) * HW] = c.f.y + b1[2 * o2 + 1];
        }
    }
}

// ================= K2: per-pixel grouped matmuls + 9x9 attention =================
// 128 threads, one pixel each. smem: weights (6912) + o1 (144*128) + o3 (144*128) + L (81*128)
#define NT2 128
#define SM_W   0
#define SM_O1  6912
#define SM_O3  (6912 + 144*NT2)
#define SM_L   (6912 + 2*144*NT2)
#define SM_TOT (6912 + 2*144*NT2 + 81*NT2)   // 54144 floats = 216576 B

__global__ void __launch_bounds__(128) attn_kernel(
    const float* __restrict__ w1_0, const float* __restrict__ w2_0, const float* __restrict__ w3_0,
    const float* __restrict__ w1_1, const float* __restrict__ w2_1, const float* __restrict__ w3_1,
    const float* __restrict__ scale)
{
    extern __shared__ float sm[];
    float* s_w  = sm + SM_W;   // w1 | w2 | w3 (2304 each)
    float* sO1  = sm + SM_O1;  // [(q*16+c)*NT2 + tid]
    float* sO3  = sm + SM_O3;
    float* sL   = sm + SM_L;   // [(p*9+q)*NT2 + tid]

    const int tid = threadIdx.x;
    const int pid = blockIdx.x * NT2 + tid;
    const int b  = pid / HW;
    const int hw = pid % HW;
    const int y = hw / Wd, x = hw % Wd;

#pragma unroll 1
    for (int br = 0; br < 2; br++) {
        const float* h  = (br ? g_h1 : g_h0) + (size_t)b * 16 * HW;
        const float* w1 = br ? w1_1 : w1_0;
        const float* w2 = br ? w2_1 : w2_0;
        const float* w3 = br ? w3_1 : w3_0;
        const int   s  = br ? 5 : 1;
        const float sc = scale[br];

        __syncthreads();   // protect smem weights from previous iteration readers
        for (int i = tid; i < 2304; i += NT2) {
            s_w[i]        = w1[i];
            s_w[2304 + i] = w2[i];
            s_w[4608 + i] = w3[i];
        }
        __syncthreads();

        // ---- phase 1: o1[q][*], o3[q][*] into smem ----
#pragma unroll 1
        for (int q = 0; q < 9; q++) {
            const int yy = y + c_dy8[q] * s, xx = x + c_dx8[q] * s;
            const bool ok = ((unsigned)yy < (unsigned)Hd) && ((unsigned)xx < (unsigned)Wd);
            const float sgn = (q == 8) ? 1.f : -1.f;
            const int off = yy * Wd + xx;
            float xv[16];
#pragma unroll
            for (int c = 0; c < 16; c++) {
                float hv = 0.f;
                if (ok) hv = h[c * HW + off];
                xv[c] = sgn * hv;
            }
            float a1[16], a3[16];
#pragma unroll
            for (int d = 0; d < 16; d++) { a1[d] = 0.f; a3[d] = 0.f; }
#pragma unroll
            for (int c = 0; c < 16; c++) {
                const float xc = xv[c];
#pragma unroll
                for (int d = 0; d < 16; d++) {
                    a1[d] += s_w[q * 256 + d * 16 + c] * xc;
                    a3[d] += s_w[4608 + q * 256 + d * 16 + c] * xc;
                }
            }
#pragma unroll
            for (int d = 0; d < 16; d++) {
                sO1[(q * 16 + d) * NT2 + tid] = a1[d];
                sO3[(q * 16 + d) * NT2 + tid] = a3[d];
            }
        }

        // ---- phase 2: o2[p], logits L[p][q] ----
#pragma unroll 1
        for (int p = 0; p < 9; p++) {
            const int yy = y + c_dy8[p] * s, xx = x + c_dx8[p] * s;
            const bool ok = ((unsigned)yy < (unsigned)Hd) && ((unsigned)xx < (unsigned)Wd);
            const float sgn = (p == 8) ? 1.f : -1.f;
            const int off = yy * Wd + xx;
            float xv[16];
#pragma unroll
            for (int c = 0; c < 16; c++) {
                float hv = 0.f;
                if (ok) hv = h[c * HW + off];
                xv[c] = sgn * hv;
            }
            float a2[16];
#pragma unroll
            for (int d = 0; d < 16; d++) a2[d] = 0.f;
#pragma unroll
            for (int c = 0; c < 16; c++) {
                const float xc = xv[c];
#pragma unroll
                for (int d = 0; d < 16; d++)
                    a2[d] += s_w[2304 + p * 256 + d * 16 + c] * xc;
            }
#pragma unroll
            for (int q = 0; q < 9; q++) {
                float acc = 0.f;
#pragma unroll
                for (int c = 0; c < 16; c++)
                    acc += a2[c] * sO1[(q * 16 + c) * NT2 + tid];
                sL[(p * 9 + q) * NT2 + tid] = sc * acc;
            }
        }

        // ---- phase 3: softmax over q, apply to o3, write cat ----
        float* outp = g_cat + ((size_t)b * 288 + br * 144) * HW + hw;
#pragma unroll 1
        for (int p = 0; p < 9; p++) {
            float l[9];
#pragma unroll
            for (int q = 0; q < 9; q++) l[q] = sL[(p * 9 + q) * NT2 + tid];
            float m = l[0];
#pragma unroll
            for (int q = 1; q < 9; q++) m = fmaxf(m, l[q]);
            float e[9], ssum = 0.f;
#pragma unroll
            for (int q = 0; q < 9; q++) { e[q] = __expf(l[q] - m); ssum += e[q]; }
            float rp[16];
#pragma unroll
            for (int c = 0; c < 16; c++) rp[c] = 0.f;
#pragma unroll
            for (int q = 0; q < 9; q++) {
                const float wq = e[q];
#pragma unroll
                for (int c = 0; c < 16; c++)
                    rp[c] += wq * sO3[(q * 16 + c) * NT2 + tid];
            }
            const float inv = 1.f / ssum;
#pragma unroll
            for (int c = 0; c < 16; c++)
                outp[(size_t)(p * 16 + c) * HW] = rp[c] * inv;
        }
    }
}

// ================= K3: final 1x1 conv: out[128] = W[128,288] @ cat =================
// 256 threads, tile 128 outs x 64 px, f32x2 over pixel pairs
__global__ void __launch_bounds__(256) out_kernel(
    const float* __restrict__ out_b, float* __restrict__ out)
{
    __shared__ __align__(16) float sW[16][128];
    __shared__ __align__(16) float sX[16][66];

    const int tid = threadIdx.x;
    const int to = tid >> 3;   // 0..31  -> 4 output channels
    const int tp = tid & 7;    // 0..7   -> 8 pixels (4 float2)
    const int b = blockIdx.y;
    const int px0 = blockIdx.x * 64;

    unsigned long long acc[4][4];
#pragma unroll
    for (int i = 0; i < 4; i++)
#pragma unroll
        for (int j = 0; j < 4; j++) acc[i][j] = 0ull;

    const float* catb = g_cat + (size_t)b * 288 * HW + px0;

#pragma unroll 1
    for (int kc = 0; kc < 18; kc++) {
        for (int idx = tid; idx < 2048; idx += 256) {
            int k = idx >> 7, o = idx & 127;
            sW[k][o] = g_wt[(kc * 16 + k) * 128 + o];
        }
        for (int idx = tid; idx < 1024; idx += 256) {
            int k = idx >> 6, j = idx & 63;
            sX[k][j] = catb[(size_t)(kc * 16 + k) * HW + j];
        }
        __syncthreads();
#pragma unroll
        for (int k = 0; k < 16; k++) {
            unsigned long long xp[4];
#pragma unroll
            for (int j = 0; j < 4; j++)
                xp[j] = *reinterpret_cast<const unsigned long long*>(&sX[k][tp * 8 + 2 * j]);
#pragma unroll
            for (int i = 0; i < 4; i++) {
                const float wv = sW[k][to * 4 + i];
                const unsigned long long w2 = pack2(wv, wv);
#pragma unroll
                for (int j = 0; j < 4; j++)
                    acc[i][j] = fma2(w2, xp[j], acc[i][j]);
            }
        }
        __syncthreads();
    }

#pragma unroll
    for (int i = 0; i < 4; i++) {
        const int o = to * 4 + i;
        const float bias = out_b[o];
        float* op = out + ((size_t)b * 128 + o) * HW + px0 + tp * 8;
#pragma unroll
        for (int j = 0; j < 4; j++) {
            F2U a; a.u = acc[i][j];
            float2 r = make_float2(a.f.x + bias, a.f.y + bias);
            *reinterpret_cast<float2*>(&op[2 * j]) = r;
        }
    }
}

// ================= launch =================
extern "C" void kernel_launch(void* const* d_in, const int* in_sizes, int n_in,
                              void* d_out, int out_size)
{
    const float* cen   = (const float*)d_in[0];
    const float* in_w0 = (const float*)d_in[1];
    const float* in_b0 = (const float*)d_in[2];
    const float* in_w1 = (const float*)d_in[3];
    const float* in_b1 = (const float*)d_in[4];
    const float* w1_0  = (const float*)d_in[5];
    const float* w2_0  = (const float*)d_in[6];
    const float* w3_0  = (const float*)d_in[7];
    const float* w1_1  = (const float*)d_in[8];
    const float* w2_1  = (const float*)d_in[9];
    const float* w3_1  = (const float*)d_in[10];
    const float* scale = (const float*)d_in[11];
    const float* out_w = (const float*)d_in[12];
    const float* out_b = (const float*)d_in[13];
    float* out = (float*)d_out;

    cudaFuncSetAttribute(attn_kernel, cudaFuncAttributeMaxDynamicSharedMemorySize,
                         SM_TOT * (int)sizeof(float));

    wt_kernel<<<144, 256>>>(out_w);
    proj_kernel<<<dim3(12, 12, 4), dim3(16, 8)>>>(cen, in_w0, in_b0, in_w1, in_b1);
    attn_kernel<<<PIX / NT2, NT2, SM_TOT * (int)sizeof(float)>>>(
        w1_0, w2_0, w3_0, w1_1, w2_1, w3_1, scale);
    out_kernel<<<dim3(HW / 64, BATCH), 256>>>(out_b, out);
}

// round 4
// speedup vs baseline: 1.5395x; 1.5395x over previous
#include <cuda_runtime.h>
#include <cuda_fp16.h>

#define Wd 192
#define Hd 192
#define HW (192*192)
#define BATCH 4
#define PIX (BATCH*HW)
#define INC 256

// ---------------- scratch (no allocations allowed) ----------------
__device__ __align__(16) float g_h0[BATCH*16*HW];
__device__ __align__(16) float g_h1[BATCH*16*HW];
__device__ __align__(16) float g_cat[(size_t)BATCH*288*HW];
__device__ __align__(16) float g_wt[288*128];

__constant__ int c_dy8[9] = {-1,-1,-1, 0, 1, 1, 1, 0, 0};
__constant__ int c_dx8[9] = {-1, 0, 1, 1, 1, 0,-1,-1, 0};

// ---------------- helpers ----------------
typedef unsigned long long ull;
union F2U { float2 f; ull u; };

__device__ __forceinline__ ull fma2(ull a, ull b, ull c) {
    ull d;
    asm("fma.rn.f32x2 %0, %1, %2, %3;" : "=l"(d) : "l"(a), "l"(b), "l"(c));
    return d;
}
__device__ __forceinline__ ull pack2(float x, float y) {
    F2U t; t.f = make_float2(x, y); return t.u;
}
__device__ __forceinline__ unsigned h2u(__half2 h) { return *(unsigned*)&h; }
__device__ __forceinline__ __half2 u2h(unsigned u) { return *(__half2*)&u; }

__device__ __forceinline__ void cp16(unsigned dst, const void* src) {
    asm volatile("cp.async.cg.shared.global [%0], [%1], 16;" :: "r"(dst), "l"(src));
}

// ================= K0: transpose out_w (128,288) -> (288,128) =================
__global__ void wt_kernel(const float* __restrict__ out_w) {
    int idx = blockIdx.x * 256 + threadIdx.x;
    if (idx < 128 * 288) {
        int o = idx / 288, i = idx % 288;
        g_wt[i * 128 + o] = out_w[idx];
    }
}

// ================= K1: fused 1x1 + 3x3 projection (256 -> 16, 16) =================
__global__ void __launch_bounds__(128) proj_kernel(
    const float* __restrict__ cen,
    const float* __restrict__ w0, const float* __restrict__ b0,
    const float* __restrict__ w1, const float* __restrict__ b1)
{
    __shared__ __align__(16) float s_cen[16][18][18];
    __shared__ __align__(16) float s_w1[16][9][16];
    __shared__ __align__(16) float s_w0[16][16];

    const int tx = threadIdx.x;
    const int ty = threadIdx.y;
    const int tid = ty * 16 + tx;
    const int x0 = blockIdx.x * 16, y0 = blockIdx.y * 16;
    const int b  = blockIdx.z;

    ull acc0[2][8], acc1[2][8];
#pragma unroll
    for (int p = 0; p < 2; p++)
#pragma unroll
        for (int o = 0; o < 8; o++) { acc0[p][o] = 0ull; acc1[p][o] = 0ull; }

#pragma unroll 1
    for (int cc = 0; cc < 16; cc++) {
        for (int idx = tid; idx < 16 * 324; idx += 128) {
            int ci = idx / 324, rem = idx % 324;
            int ly = rem / 18, lx = rem % 18;
            int gy = y0 - 1 + ly, gx = x0 - 1 + lx;
            float v = 0.f;
            if ((unsigned)gy < (unsigned)Hd && (unsigned)gx < (unsigned)Wd)
                v = cen[(size_t)(b * INC + cc * 16 + ci) * HW + gy * Wd + gx];
            s_cen[ci][ly][lx] = v;
        }
        for (int idx = tid; idx < 2304; idx += 128) {
            int ci = idx / 144, rem = idx % 144;
            int t = rem / 16, o = rem % 16;
            s_w1[ci][t][o] = w1[(o * INC + cc * 16 + ci) * 9 + t];
        }
        for (int ii = tid; ii < 256; ii += 128) {
            int ci = ii / 16, o = ii % 16;
            s_w0[ci][o] = w0[o * INC + cc * 16 + ci];
        }
        __syncthreads();

#pragma unroll 1
        for (int ci = 0; ci < 16; ci++) {
#pragma unroll
            for (int px = 0; px < 2; px++) {
                const int ly = ty + px * 8;
                float v[9];
#pragma unroll
                for (int r = 0; r < 3; r++)
#pragma unroll
                    for (int c = 0; c < 3; c++)
                        v[r * 3 + c] = s_cen[ci][ly + r][tx + c];

                ull cv = pack2(v[4], v[4]);
                const ull* w0p = reinterpret_cast<const ull*>(&s_w0[ci][0]);
#pragma unroll
                for (int o2 = 0; o2 < 8; o2++)
                    acc0[px][o2] = fma2(cv, w0p[o2], acc0[px][o2]);
#pragma unroll
                for (int t = 0; t < 9; t++) {
                    ull tv = pack2(v[t], v[t]);
                    const ull* wp = reinterpret_cast<const ull*>(&s_w1[ci][t][0]);
#pragma unroll
                    for (int o2 = 0; o2 < 8; o2++)
                        acc1[px][o2] = fma2(tv, wp[o2], acc1[px][o2]);
                }
            }
        }
        __syncthreads();
    }

#pragma unroll
    for (int px = 0; px < 2; px++) {
        const int y = y0 + ty + px * 8, x = x0 + tx;
        const size_t base = (size_t)b * 16 * HW + (size_t)y * Wd + x;
#pragma unroll
        for (int o2 = 0; o2 < 8; o2++) {
            F2U a; a.u = acc0[px][o2];
            g_h0[base + (size_t)(2 * o2) * HW]     = a.f.x + b0[2 * o2];
            g_h0[base + (size_t)(2 * o2 + 1) * HW] = a.f.y + b0[2 * o2 + 1];
            F2U c; c.u = acc1[px][o2];
            g_h1[base + (size_t)(2 * o2) * HW]     = c.f.x + b1[2 * o2];
            g_h1[base + (size_t)(2 * o2 + 1) * HW] = c.f.y + b1[2 * o2 + 1];
        }
    }
}

// ================= K2: per-pixel attention, 2 px/thread, f32x2, fp16 staging ====
#define NT2 128
#define SO1_OFF 6912
#define SO3_OFF (6912 + 9*8*2*NT2)           // + 18432
#define SMTOT   (6912 + 2*9*8*2*NT2)         // 43776 words -> 175104 B

__global__ void __launch_bounds__(NT2) attn_kernel(
    const float* __restrict__ w1_0, const float* __restrict__ w2_0, const float* __restrict__ w3_0,
    const float* __restrict__ w1_1, const float* __restrict__ w2_1, const float* __restrict__ w3_1,
    const float* __restrict__ scale)
{
    extern __shared__ float sm[];
    float* s_w = sm;                                  // w1t | w2t | w3t, [(g*16+c)*16+d]
    unsigned* sO1 = (unsigned*)(sm + SO1_OFF);        // half2 [( (q*8+dp)*2+pxi )*NT2+tid]
    unsigned* sO3 = (unsigned*)(sm + SO3_OFF);

    const int tid = threadIdx.x;
    const int pid0 = blockIdx.x * (2 * NT2) + 2 * tid;
    const int b  = pid0 / HW;
    const int hw0 = pid0 % HW;
    const int y = hw0 / Wd, x0 = hw0 % Wd;

#pragma unroll 1
    for (int br = 0; br < 2; br++) {
        const float* h  = (br ? g_h1 : g_h0) + (size_t)b * 16 * HW;
        const float* w1 = br ? w1_1 : w1_0;
        const float* w2 = br ? w2_1 : w2_0;
        const float* w3 = br ? w3_1 : w3_0;
        const int   s  = br ? 5 : 1;
        const float sc = scale[br];

        __syncthreads();
        // stage transposed weights: s_w[(g*16+c)*16+d] = w[g*256+d*16+c]
        for (int i = tid; i < 2304; i += NT2) {
            int g = i >> 8; int rem = i & 255;
            int d = rem >> 4, c = rem & 15;
            int tix = ((g * 16 + c) << 4) + d;
            s_w[tix]        = w1[i];
            s_w[2304 + tix] = w2[i];
            s_w[4608 + tix] = w3[i];
        }
        __syncthreads();

        // ---------- phase 1: o1[q], o3[q] -> fp16 smem ----------
#pragma unroll 1
        for (int q = 0; q < 9; q++) {
            const int yy = y + c_dy8[q] * s;
            const int xxa = x0 + c_dx8[q] * s;
            const bool oky = (unsigned)yy < (unsigned)Hd;
            const bool ok0 = oky && (unsigned)xxa < (unsigned)Wd;
            const bool ok1 = oky && (unsigned)(xxa + 1) < (unsigned)Wd;
            const float sgn = (q == 8) ? 1.f : -1.f;
            const float* hrow = h + yy * Wd;

            float xv0[16], xv1[16];
#pragma unroll
            for (int c = 0; c < 16; c++) {
                float v0 = ok0 ? hrow[c * HW + xxa] : 0.f;
                float v1 = ok1 ? hrow[c * HW + xxa + 1] : 0.f;
                xv0[c] = sgn * v0; xv1[c] = sgn * v1;
            }
            // o1 pass
            {
                ull a[2][8];
#pragma unroll
                for (int dp = 0; dp < 8; dp++) { a[0][dp] = 0ull; a[1][dp] = 0ull; }
#pragma unroll
                for (int c = 0; c < 16; c++) {
                    ull xc0 = pack2(xv0[c], xv0[c]);
                    ull xc1 = pack2(xv1[c], xv1[c]);
                    const ull* wp = (const ull*)(s_w + (((q * 16 + c) << 4)));
#pragma unroll
                    for (int dp = 0; dp < 8; dp++) {
                        a[0][dp] = fma2(xc0, wp[dp], a[0][dp]);
                        a[1][dp] = fma2(xc1, wp[dp], a[1][dp]);
                    }
                }
#pragma unroll
                for (int pxi = 0; pxi < 2; pxi++)
#pragma unroll
                    for (int dp = 0; dp < 8; dp++) {
                        F2U t; t.u = a[pxi][dp];
                        sO1[((((q << 3) + dp) << 1) + pxi) * NT2 + tid] =
                            h2u(__float22half2_rn(t.f));
                    }
            }
            // o3 pass
            {
                ull a[2][8];
#pragma unroll
                for (int dp = 0; dp < 8; dp++) { a[0][dp] = 0ull; a[1][dp] = 0ull; }
#pragma unroll
                for (int c = 0; c < 16; c++) {
                    ull xc0 = pack2(xv0[c], xv0[c]);
                    ull xc1 = pack2(xv1[c], xv1[c]);
                    const ull* wp = (const ull*)(s_w + 4608 + (((q * 16 + c) << 4)));
#pragma unroll
                    for (int dp = 0; dp < 8; dp++) {
                        a[0][dp] = fma2(xc0, wp[dp], a[0][dp]);
                        a[1][dp] = fma2(xc1, wp[dp], a[1][dp]);
                    }
                }
#pragma unroll
                for (int pxi = 0; pxi < 2; pxi++)
#pragma unroll
                    for (int dp = 0; dp < 8; dp++) {
                        F2U t; t.u = a[pxi][dp];
                        sO3[((((q << 3) + dp) << 1) + pxi) * NT2 + tid] =
                            h2u(__float22half2_rn(t.f));
                    }
            }
        }

        // ---------- phase 2+3: o2[p], logits, softmax, apply ----------
        float* gco = g_cat + ((size_t)b * 288 + br * 144) * HW + hw0;
#pragma unroll 1
        for (int p = 0; p < 9; p++) {
            const int yy = y + c_dy8[p] * s;
            const int xxa = x0 + c_dx8[p] * s;
            const bool oky = (unsigned)yy < (unsigned)Hd;
            const bool ok0 = oky && (unsigned)xxa < (unsigned)Wd;
            const bool ok1 = oky && (unsigned)(xxa + 1) < (unsigned)Wd;
            const float sgn = (p == 8) ? 1.f : -1.f;
            const float* hrow = h + yy * Wd;

            ull a2[2][8];
#pragma unroll
            for (int dp = 0; dp < 8; dp++) { a2[0][dp] = 0ull; a2[1][dp] = 0ull; }
#pragma unroll
            for (int c = 0; c < 16; c++) {
                float v0 = ok0 ? hrow[c * HW + xxa] : 0.f;
                float v1 = ok1 ? hrow[c * HW + xxa + 1] : 0.f;
                ull xc0 = pack2(sgn * v0, sgn * v0);
                ull xc1 = pack2(sgn * v1, sgn * v1);
                const ull* wp = (const ull*)(s_w + 2304 + (((p * 16 + c) << 4)));
#pragma unroll
                for (int dp = 0; dp < 8; dp++) {
                    a2[0][dp] = fma2(xc0, wp[dp], a2[0][dp]);
                    a2[1][dp] = fma2(xc1, wp[dp], a2[1][dp]);
                }
            }
            // logits
            float l0[9], l1[9];
#pragma unroll
            for (int q = 0; q < 9; q++) {
                ull acc0 = 0ull, acc1 = 0ull;
#pragma unroll
                for (int dp = 0; dp < 8; dp++) {
                    F2U u0; u0.f = __half22float2(u2h(sO1[((((q << 3) + dp) << 1) + 0) * NT2 + tid]));
                    F2U u1; u1.f = __half22float2(u2h(sO1[((((q << 3) + dp) << 1) + 1) * NT2 + tid]));
                    acc0 = fma2(a2[0][dp], u0.u, acc0);
                    acc1 = fma2(a2[1][dp], u1.u, acc1);
                }
                F2U r0; r0.u = acc0; l0[q] = sc * (r0.f.x + r0.f.y);
                F2U r1; r1.u = acc1; l1[q] = sc * (r1.f.x + r1.f.y);
            }
            // softmax (in-place exp)
            float m0 = l0[0], m1 = l1[0];
#pragma unroll
            for (int q = 1; q < 9; q++) { m0 = fmaxf(m0, l0[q]); m1 = fmaxf(m1, l1[q]); }
            float ss0 = 0.f, ss1 = 0.f;
#pragma unroll
            for (int q = 0; q < 9; q++) {
                l0[q] = __expf(l0[q] - m0); ss0 += l0[q];
                l1[q] = __expf(l1[q] - m1); ss1 += l1[q];
            }
            // apply
            ull rp0[8], rp1[8];
#pragma unroll
            for (int dp = 0; dp < 8; dp++) { rp0[dp] = 0ull; rp1[dp] = 0ull; }
#pragma unroll
            for (int q = 0; q < 9; q++) {
                ull e0 = pack2(l0[q], l0[q]);
                ull e1 = pack2(l1[q], l1[q]);
#pragma unroll
                for (int dp = 0; dp < 8; dp++) {
                    F2U u0; u0.f = __half22float2(u2h(sO3[((((q << 3) + dp) << 1) + 0) * NT2 + tid]));
                    F2U u1; u1.f = __half22float2(u2h(sO3[((((q << 3) + dp) << 1) + 1) * NT2 + tid]));
                    rp0[dp] = fma2(e0, u0.u, rp0[dp]);
                    rp1[dp] = fma2(e1, u1.u, rp1[dp]);
                }
            }
            const float inv0 = 1.f / ss0, inv1 = 1.f / ss1;
#pragma unroll
            for (int dp = 0; dp < 8; dp++) {
                F2U t0; t0.u = rp0[dp];
                F2U t1; t1.u = rp1[dp];
                float2 wlo = make_float2(t0.f.x * inv0, t1.f.x * inv1);
                float2 whi = make_float2(t0.f.y * inv0, t1.f.y * inv1);
                *(float2*)&gco[(size_t)((p << 4) + 2 * dp) * HW]     = wlo;
                *(float2*)&gco[(size_t)((p << 4) + 2 * dp + 1) * HW] = whi;
            }
        }
    }
}

// ================= K3: final 1x1 conv, 128x128 tile, 8x8 per thread, cp.async ===
__global__ void __launch_bounds__(256) out_kernel(
    const float* __restrict__ out_b, float* __restrict__ out)
{
    __shared__ __align__(16) float sW[2][16][128];
    __shared__ __align__(16) float sX[2][16][128];

    const int tid = threadIdx.x;
    const int to = tid >> 4;   // 0..15 -> 8 outputs
    const int tp = tid & 15;   // 0..15 -> 8 pixels
    const int b = blockIdx.y;
    const int px0 = blockIdx.x * 128;
    const float* catb = g_cat + (size_t)b * 288 * HW + px0;

    const unsigned swb = (unsigned)__cvta_generic_to_shared(&sW[0][0][0]);
    const unsigned sxb = (unsigned)__cvta_generic_to_shared(&sX[0][0][0]);

    ull acc[8][4];
#pragma unroll
    for (int i = 0; i < 8; i++)
#pragma unroll
        for (int j = 0; j < 4; j++) acc[i][j] = 0ull;

    // prologue stage chunk 0 into buf 0
    {
#pragma unroll
        for (int i = 0; i < 2; i++) {
            int idx = tid + i * 256;
            int k = idx >> 5, c = (idx & 31) << 2;
            cp16(swb + (unsigned)((k * 128 + c) * 4), &g_wt[(0 * 16 + k) * 128 + c]);
            cp16(sxb + (unsigned)((k * 128 + c) * 4), &catb[(size_t)(0 * 16 + k) * HW + c]);
        }
        asm volatile("cp.async.commit_group;");
    }

#pragma unroll 1
    for (int kc = 0; kc < 18; kc++) {
        if (kc < 17) {
            const int nb = (kc + 1) & 1;
            const unsigned off = (unsigned)(nb * 16 * 128 * 4);
#pragma unroll
            for (int i = 0; i < 2; i++) {
                int idx = tid + i * 256;
                int k = idx >> 5, c = (idx & 31) << 2;
                cp16(swb + off + (unsigned)((k * 128 + c) * 4),
                     &g_wt[((kc + 1) * 16 + k) * 128 + c]);
                cp16(sxb + off + (unsigned)((k * 128 + c) * 4),
                     &catb[(size_t)((kc + 1) * 16 + k) * HW + c]);
            }
            asm volatile("cp.async.commit_group;");
            asm volatile("cp.async.wait_group 1;");
        } else {
            asm volatile("cp.async.wait_group 0;");
        }
        __syncthreads();

        const int buf = kc & 1;
#pragma unroll
        for (int k = 0; k < 16; k++) {
            const ull* xr = (const ull*)&sX[buf][k][tp * 8];
            ull x0 = xr[0], x1 = xr[1], x2 = xr[2], x3 = xr[3];
            const float* wr = &sW[buf][k][to * 8];
#pragma unroll
            for (int i = 0; i < 8; i++) {
                ull wp = pack2(wr[i], wr[i]);
                acc[i][0] = fma2(wp, x0, acc[i][0]);
                acc[i][1] = fma2(wp, x1, acc[i][1]);
                acc[i][2] = fma2(wp, x2, acc[i][2]);
                acc[i][3] = fma2(wp, x3, acc[i][3]);
            }
        }
        __syncthreads();
    }

#pragma unroll
    for (int i = 0; i < 8; i++) {
        const int o = to * 8 + i;
        const float bias = out_b[o];
        float* op = out + ((size_t)b * 128 + o) * HW + px0 + tp * 8;
#pragma unroll
        for (int j = 0; j < 4; j++) {
            F2U a; a.u = acc[i][j];
            *(float2*)&op[2 * j] = make_float2(a.f.x + bias, a.f.y + bias);
        }
    }
}

// ================= launch =================
extern "C" void kernel_launch(void* const* d_in, const int* in_sizes, int n_in,
                              void* d_out, int out_size)
{
    const float* cen   = (const float*)d_in[0];
    const float* in_w0 = (const float*)d_in[1];
    const float* in_b0 = (const float*)d_in[2];
    const float* in_w1 = (const float*)d_in[3];
    const float* in_b1 = (const float*)d_in[4];
    const float* w1_0  = (const float*)d_in[5];
    const float* w2_0  = (const float*)d_in[6];
    const float* w3_0  = (const float*)d_in[7];
    const float* w1_1  = (const float*)d_in[8];
    const float* w2_1  = (const float*)d_in[9];
    const float* w3_1  = (const float*)d_in[10];
    const float* scale = (const float*)d_in[11];
    const float* out_w = (const float*)d_in[12];
    const float* out_b = (const float*)d_in[13];
    float* out = (float*)d_out;

    cudaFuncSetAttribute(attn_kernel, cudaFuncAttributeMaxDynamicSharedMemorySize,
                         SMTOT * (int)sizeof(float));

    wt_kernel<<<144, 256>>>(out_w);
    proj_kernel<<<dim3(12, 12, 4), dim3(16, 8)>>>(cen, in_w0, in_b0, in_w1, in_b1);
    attn_kernel<<<PIX / (2 * NT2), NT2, SMTOT * (int)sizeof(float)>>>(
        w1_0, w2_0, w3_0, w1_1, w2_1, w3_1, scale);
    out_kernel<<<dim3(HW / 128, BATCH), 256>>>(out_b, out);
}